// round 3
// baseline (speedup 1.0000x reference)
#include <cuda_runtime.h>
#include <cuda_bf16.h>
#include <cstdint>

// ============================================================================
// Feature gate: tcgen05 only exists on the sm_103a (arch-accelerated) pass.
// On a plain sm_103 pass the tcgen05 kernel compiles to an empty body and the
// mma.sync fallback does the work. A probe kernel records which pass is live.
// ============================================================================
#if defined(__CUDA_ARCH__) && defined(__CUDA_ARCH_FEAT_SM103_ALL)
#define HAS_TC 1
#else
#define HAS_TC 0
#endif

// ============================================================================
// Problem constants
// ============================================================================
#define IN_DIM   4096
#define OUT_DIM  4096
#define RANK     64
#define M_TOTAL  16384            // 4 * 4096 rows of x

#define NSEG     3                // x_hi*w_hi + x_lo*w_hi + x_hi*w_lo
#define NCH      (NSEG * (IN_DIM / 64))   // 192 chunks of k=64 bf16

// ---- tcgen05 path tiling ----
#define TILE_M   128
#define TILE_N   256
#define A_BYTES  (TILE_M * 128)   // 16384
#define B_BYTES  (TILE_N * 128)   // 32768
#define STAGE_BYTES (A_BYTES + B_BYTES)       // 49152
#define SMEM_STAGE0 1024
#define SMEM_TC  (SMEM_STAGE0 + 4 * STAGE_BYTES)   // 197632
#define GEMM_IDESC 0x8400490u     // f16-kind, bf16 x bf16 -> f32, M=128, N=256

// ---- fallback path tiling (same CTA tile, 512 threads) ----
#define SMEM_FB  (4 * STAGE_BYTES)                 // 196608

// ============================================================================
// Device scratch (static globals — no runtime allocation)
// ============================================================================
__device__ __align__(256) __nv_bfloat16 g_xhi[(size_t)M_TOTAL * IN_DIM];
__device__ __align__(256) __nv_bfloat16 g_xlo[(size_t)M_TOTAL * IN_DIM];
__device__ __align__(256) __nv_bfloat16 g_whi[(size_t)OUT_DIM * IN_DIM];
__device__ __align__(256) __nv_bfloat16 g_wlo[(size_t)OUT_DIM * IN_DIM];
__device__ __align__(256) float         g_aprime[OUT_DIM * 2 * RANK];
__device__ int g_has_tc;

// ============================================================================
// Common PTX helpers (all legal on plain sm_103)
// ============================================================================
__device__ __forceinline__ uint32_t smem_to_u32(const void* p) {
    uint32_t a;
    asm("{ .reg .u64 t; cvta.to.shared.u64 t, %1; cvt.u32.u64 %0, t; }"
        : "=r"(a) : "l"(p));
    return a;
}

__device__ __forceinline__ void cp_async16(uint32_t dst, const void* src) {
    asm volatile("cp.async.cg.shared.global [%0], [%1], 16;"
                 :: "r"(dst), "l"(src));
}
#define CP_COMMIT() asm volatile("cp.async.commit_group;" ::: "memory")
#define CP_WAIT(n)  asm volatile("cp.async.wait_group %0;" :: "n"(n) : "memory")

__device__ __forceinline__ void ldsm_x4(uint32_t* r, uint32_t addr) {
    asm volatile("ldmatrix.sync.aligned.m8n8.x4.shared.b16 {%0,%1,%2,%3}, [%4];"
        : "=r"(r[0]), "=r"(r[1]), "=r"(r[2]), "=r"(r[3]) : "r"(addr));
}

__device__ __forceinline__ void mma16816(float* d, const uint32_t* a,
                                         const uint32_t* b) {
    asm volatile(
        "mma.sync.aligned.m16n8k16.row.col.f32.bf16.bf16.f32 "
        "{%0,%1,%2,%3}, {%4,%5,%6,%7}, {%8,%9}, {%0,%1,%2,%3};"
        : "+f"(d[0]), "+f"(d[1]), "+f"(d[2]), "+f"(d[3])
        : "r"(a[0]), "r"(a[1]), "r"(a[2]), "r"(a[3]), "r"(b[0]), "r"(b[1]));
}

// ============================================================================
// Probe: record whether the loaded SASS is the sm_103a pass
// ============================================================================
__global__ void probe_kernel() { g_has_tc = HAS_TC; }

// ============================================================================
// Kernel A0: A' = [ P*diag(lam) | -P_b*diag(lam_b) ]  (4096 x 128)
// ============================================================================
__global__ void build_aprime_kernel(const float* __restrict__ p_w,
                                    const float* __restrict__ lam,
                                    const float* __restrict__ bp_w,
                                    const float* __restrict__ blam) {
    int idx = blockIdx.x * 256 + threadIdx.x;   // < 4096*128
    int o = idx >> 7;
    int r = idx & 127;
    float v;
    if (r < RANK) v =  p_w[o * RANK + r] * lam[r];
    else          v = -(bp_w[o * RANK + (r - RANK)] * blam[r - RANK]);
    g_aprime[idx] = v;
}

// ============================================================================
// Kernel A1: W_eff = W_org + A' @ [Q ; Q_b], split into bf16 hi/lo
// ============================================================================
__global__ __launch_bounds__(256) void fold_w_kernel(
    const float* __restrict__ W_org,
    const float* __restrict__ q_w,
    const float* __restrict__ base_q_w) {
    __shared__ float sA[16][128];
    const int o0 = blockIdx.y * 16;
    const int i0 = blockIdx.x * 1024;
    const int tid = threadIdx.x;

    for (int t = tid; t < 16 * 128; t += 256)
        sA[t >> 7][t & 127] = g_aprime[(size_t)(o0 + (t >> 7)) * 128 + (t & 127)];
    __syncthreads();

    const int i = i0 + tid * 4;
    float4 acc[16];
#pragma unroll
    for (int oo = 0; oo < 16; ++oo)
        acc[oo] = *(const float4*)(W_org + (size_t)(o0 + oo) * IN_DIM + i);

#pragma unroll 4
    for (int r = 0; r < RANK; ++r) {
        float4 b = *(const float4*)(q_w + (size_t)r * IN_DIM + i);
#pragma unroll
        for (int oo = 0; oo < 16; ++oo) {
            float s = sA[oo][r];
            acc[oo].x += s * b.x; acc[oo].y += s * b.y;
            acc[oo].z += s * b.z; acc[oo].w += s * b.w;
        }
    }
#pragma unroll 4
    for (int r = 0; r < RANK; ++r) {
        float4 b = *(const float4*)(base_q_w + (size_t)r * IN_DIM + i);
#pragma unroll
        for (int oo = 0; oo < 16; ++oo) {
            float s = sA[oo][RANK + r];
            acc[oo].x += s * b.x; acc[oo].y += s * b.y;
            acc[oo].z += s * b.z; acc[oo].w += s * b.w;
        }
    }

#pragma unroll
    for (int oo = 0; oo < 16; ++oo) {
        size_t base = (size_t)(o0 + oo) * IN_DIM + i;
        float v[4] = {acc[oo].x, acc[oo].y, acc[oo].z, acc[oo].w};
        __nv_bfloat16 h[4], l[4];
#pragma unroll
        for (int k = 0; k < 4; ++k) {
            h[k] = __float2bfloat16(v[k]);
            l[k] = __float2bfloat16(v[k] - __bfloat162float(h[k]));
        }
        __nv_bfloat162* ph = (__nv_bfloat162*)(g_whi + base);
        __nv_bfloat162* pl = (__nv_bfloat162*)(g_wlo + base);
        __nv_bfloat162 h01; h01.x = h[0]; h01.y = h[1];
        __nv_bfloat162 h23; h23.x = h[2]; h23.y = h[3];
        __nv_bfloat162 l01; l01.x = l[0]; l01.y = l[1];
        __nv_bfloat162 l23; l23.x = l[2]; l23.y = l[3];
        ph[0] = h01; ph[1] = h23;
        pl[0] = l01; pl[1] = l23;
    }
}

// ============================================================================
// Kernel B: split x into bf16 hi/lo
// ============================================================================
__global__ __launch_bounds__(256) void split_x_kernel(const float4* __restrict__ x) {
    size_t i = (size_t)blockIdx.x * 256 + threadIdx.x;  // float4 index
    float4 v = x[i];
    float f[4] = {v.x, v.y, v.z, v.w};
    __nv_bfloat16 h[4], l[4];
#pragma unroll
    for (int k = 0; k < 4; ++k) {
        h[k] = __float2bfloat16(f[k]);
        l[k] = __float2bfloat16(f[k] - __bfloat162float(h[k]));
    }
    __nv_bfloat162 h01; h01.x = h[0]; h01.y = h[1];
    __nv_bfloat162 h23; h23.x = h[2]; h23.y = h[3];
    __nv_bfloat162 l01; l01.x = l[0]; l01.y = l[1];
    __nv_bfloat162 l23; l23.x = l[2]; l23.y = l[3];
    ((__nv_bfloat162*)g_xhi)[i * 2 + 0] = h01;
    ((__nv_bfloat162*)g_xhi)[i * 2 + 1] = h23;
    ((__nv_bfloat162*)g_xlo)[i * 2 + 0] = l01;
    ((__nv_bfloat162*)g_xlo)[i * 2 + 1] = l23;
}

// ============================================================================
// tcgen05-only helpers (emitted only on the sm_103a pass)
// ============================================================================
#if HAS_TC
__device__ __forceinline__ uint32_t elect_one_pred() {
    uint32_t pred;
    asm volatile(
        "{\n\t.reg .pred p;\n\t"
        "elect.sync _|p, 0xFFFFFFFF;\n\t"
        "selp.b32 %0, 1, 0, p;\n\t}"
        : "=r"(pred));
    return pred;
}

#define TCGEN05_ALLOC(smem_addr, nCols) \
    asm volatile("tcgen05.alloc.cta_group::1.sync.aligned.shared::cta.b32 [%0], %1;" \
        :: "r"((uint32_t)(smem_addr)), "r"((uint32_t)(nCols)) : "memory")
#define TCGEN05_DEALLOC(tmem_addr, nCols) \
    asm volatile("tcgen05.dealloc.cta_group::1.sync.aligned.b32 %0, %1;" \
        :: "r"(tmem_addr), "r"((uint32_t)(nCols)))
#define TCGEN05_RELINQ() \
    asm volatile("tcgen05.relinquish_alloc_permit.cta_group::1.sync.aligned;")
#define TCGEN05_COMMIT(mbar) \
    asm volatile("tcgen05.commit.cta_group::1.mbarrier::arrive::one.shared::cluster.b64 [%0];" \
        :: "r"((uint32_t)(mbar)) : "memory")
#define TCGEN05_FENCE_AFTER() \
    asm volatile("tcgen05.fence::after_thread_sync;" ::: "memory")
#define TCGEN05_FENCE_BEFORE() \
    asm volatile("tcgen05.fence::before_thread_sync;" ::: "memory")
#define TCGEN05_WAIT_LD() \
    asm volatile("tcgen05.wait::ld.sync.aligned;" ::: "memory")
#define FENCE_PROXY_ASYNC_SHARED_CTA() \
    asm volatile("fence.proxy.async.shared::cta;" ::: "memory")
#define MBARRIER_INIT(mbar, cnt) \
    asm volatile("mbarrier.init.shared.b64 [%0], %1;" \
        :: "r"((uint32_t)(mbar)), "r"((uint32_t)(cnt)) : "memory")
#define MBARRIER_WAIT_PARITY(mbar, parity) do { \
    uint32_t _m = (uint32_t)(mbar); uint32_t _p = (uint32_t)(parity); uint32_t _d; \
    asm volatile("{\n\t.reg .pred p;\n\t" \
        "mbarrier.try_wait.parity.acquire.cta.shared::cta.b64 p, [%1], %2;\n\t" \
        "selp.b32 %0, 1, 0, p;\n\t}" : "=r"(_d) : "r"(_m), "r"(_p) : "memory"); \
    if (!_d) { \
        asm volatile("{\n\t.reg .pred P1;\n\t" \
            "WAIT_LOOP_%=:\n\t" \
            "mbarrier.try_wait.parity.acquire.cta.shared::cta.b64 P1, [%0], %1, 0x989680;\n\t" \
            "@P1 bra.uni WAIT_DONE_%=;\n\t" \
            "bra.uni WAIT_LOOP_%=;\n\t" \
            "WAIT_DONE_%=:\n\t}" :: "r"(_m), "r"(_p) : "memory"); \
    } \
} while (0)
#define TCGEN05_LD_32X32B_X32(r, tmem_addr) \
    asm volatile( \
        "tcgen05.ld.sync.aligned.32x32b.x32.b32 " \
        "{%0, %1, %2, %3, %4, %5, %6, %7, " \
        " %8, %9, %10, %11, %12, %13, %14, %15, " \
        " %16, %17, %18, %19, %20, %21, %22, %23, " \
        " %24, %25, %26, %27, %28, %29, %30, %31}, [%32];" \
        : "=r"((r)[0]),  "=r"((r)[1]),  "=r"((r)[2]),  "=r"((r)[3]), \
          "=r"((r)[4]),  "=r"((r)[5]),  "=r"((r)[6]),  "=r"((r)[7]), \
          "=r"((r)[8]),  "=r"((r)[9]),  "=r"((r)[10]), "=r"((r)[11]), \
          "=r"((r)[12]), "=r"((r)[13]), "=r"((r)[14]), "=r"((r)[15]), \
          "=r"((r)[16]), "=r"((r)[17]), "=r"((r)[18]), "=r"((r)[19]), \
          "=r"((r)[20]), "=r"((r)[21]), "=r"((r)[22]), "=r"((r)[23]), \
          "=r"((r)[24]), "=r"((r)[25]), "=r"((r)[26]), "=r"((r)[27]), \
          "=r"((r)[28]), "=r"((r)[29]), "=r"((r)[30]), "=r"((r)[31]) \
        : "r"(tmem_addr))

static constexpr uint64_t SMEM_DESC_BASE_SW128 =
      (uint64_t(2)  << 61) | (uint64_t(1) << 46)
    | (uint64_t(64) << 32) | (uint64_t(1) << 16);
#define MAKE_SMEM_DESC(base_addr) \
    (SMEM_DESC_BASE_SW128 | ((uint64_t)((base_addr) >> 4) & 0x3FFF))

__device__ __forceinline__ void mma_f16_ss(uint32_t d_tmem, uint64_t a_desc,
                                           uint64_t b_desc, uint32_t idesc,
                                           uint32_t enable_d) {
    asm volatile(
        "{\n\t.reg .pred p;\n\t"
        "setp.ne.u32 p, %4, 0;\n\t"
        "tcgen05.mma.cta_group::1.kind::f16 [%0], %1, %2, %3, {%5, %5, %5, %5}, p;\n\t"
        "}"
        :: "r"(d_tmem), "l"(a_desc), "l"(b_desc), "r"(idesc),
           "r"(enable_d), "r"(0u)
        : "memory");
}
#endif // HAS_TC

// ============================================================================
// GEMM (tcgen05 path) — body only exists on the sm_103a pass
// ============================================================================
__global__ __launch_bounds__(256, 1)
void gemm_tc_kernel(float* __restrict__ out) {
#if HAS_TC
    extern __shared__ char smem[];
    const uint32_t smem_base = smem_to_u32(smem);
    const int tid = threadIdx.x;
    const int wid = tid >> 5;
    const int lid = tid & 31;
    const int m0 = blockIdx.y * TILE_M;
    const int n0 = blockIdx.x * TILE_N;

    if (wid == 0) {
        TCGEN05_ALLOC(smem_base + 64, 256);
        TCGEN05_RELINQ();
    }
    if (tid == 0) {
#pragma unroll
        for (int s = 0; s < 4; ++s) MBARRIER_INIT(smem_base + 8 * s, 1);
    }
    __syncthreads();

    uint32_t tmem;
    asm volatile("ld.shared.b32 %0, [%1];" : "=r"(tmem) : "r"(smem_base + 64));

    auto load_chunk = [&](int c) {
        const int st = c & 3;
        const int s  = c >> 6;
        const int k0 = (c & 63) << 6;
        const __nv_bfloat16* Ab = ((s == 1) ? g_xlo : g_xhi) + (size_t)m0 * IN_DIM + k0;
        const __nv_bfloat16* Bb = ((s == 2) ? g_wlo : g_whi) + (size_t)n0 * IN_DIM + k0;
        const uint32_t sa = smem_base + SMEM_STAGE0 + st * STAGE_BYTES;
        const uint32_t sb = sa + A_BYTES;
#pragma unroll
        for (int it = 0; it < 4; ++it) {
            int i = tid + it * 256;
            int row = i >> 3, j = i & 7;
            uint32_t off = (uint32_t)(row * 128 + j * 16);
            uint32_t dst = sa + (off ^ ((off >> 3) & 0x70));
            cp_async16(dst, Ab + (size_t)row * IN_DIM + j * 8);
        }
#pragma unroll
        for (int it = 0; it < 8; ++it) {
            int i = tid + it * 256;
            int row = i >> 3, j = i & 7;
            uint32_t off = (uint32_t)(row * 128 + j * 16);
            uint32_t dst = sb + (off ^ ((off >> 3) & 0x70));
            cp_async16(dst, Bb + (size_t)row * IN_DIM + j * 8);
        }
        CP_COMMIT();
    };

    load_chunk(0);
    load_chunk(1);

    for (int c = 0; c < NCH; ++c) {
        if (c >= 2) {
            int w = c - 2;
            MBARRIER_WAIT_PARITY(smem_base + 8 * (w & 3), (w >> 2) & 1);
        }
        if (c + 2 < NCH) { load_chunk(c + 2); CP_WAIT(2); }
        else if (c + 1 < NCH) { CP_WAIT(1); }
        else { CP_WAIT(0); }
        FENCE_PROXY_ASYNC_SHARED_CTA();
        __syncthreads();

        if (wid == 0) {
            if (elect_one_pred()) {
                const int st = c & 3;
                const uint32_t sa = smem_base + SMEM_STAGE0 + st * STAGE_BYTES;
                const uint64_t ad = MAKE_SMEM_DESC(sa);
                const uint64_t bd = MAKE_SMEM_DESC(sa + A_BYTES);
#pragma unroll
                for (int i = 0; i < 4; ++i)
                    mma_f16_ss(tmem, ad + i * 2, bd + i * 2, GEMM_IDESC,
                               (c > 0 || i > 0) ? 1u : 0u);
                TCGEN05_COMMIT(smem_base + 8 * st);
            }
        }
    }

    for (int w = NCH - 2; w < NCH; ++w)
        MBARRIER_WAIT_PARITY(smem_base + 8 * (w & 3), (w >> 2) & 1);
    TCGEN05_FENCE_AFTER();

    {
        const int sub  = wid & 3;
        const int half = wid >> 2;
        const uint32_t lane_off = ((uint32_t)sub) << 21;
        const int m = m0 + sub * 32 + lid;
        float* orow = out + (size_t)m * OUT_DIM + n0 + half * 128;
#pragma unroll
        for (int cc = 0; cc < 4; ++cc) {
            uint32_t r[32];
            TCGEN05_LD_32X32B_X32(r, tmem + lane_off + (uint32_t)(half * 128 + cc * 32));
            TCGEN05_WAIT_LD();
            float* dst = orow + cc * 32;
#pragma unroll
            for (int q = 0; q < 8; ++q) {
                float4 v;
                v.x = __uint_as_float(r[4 * q + 0]);
                v.y = __uint_as_float(r[4 * q + 1]);
                v.z = __uint_as_float(r[4 * q + 2]);
                v.w = __uint_as_float(r[4 * q + 3]);
                ((float4*)dst)[q] = v;
            }
        }
        TCGEN05_FENCE_BEFORE();
    }

    __syncthreads();
    if (wid == 0) TCGEN05_DEALLOC(tmem, 256);
#else
    (void)out;   // empty on plain sm_103 pass; fallback kernel does the work
#endif
}

// ============================================================================
// GEMM (mma.sync fallback) — 128x256 CTA tile, 512 threads (4x4 warps,
// 32x64 warp tiles), 4-stage cp.async ring, xor-swizzled smem, bf16 split-3.
// ============================================================================
__global__ __launch_bounds__(512, 1)
void gemm_fb_kernel(float* __restrict__ out) {
    if (g_has_tc) return;   // tcgen05 path is live; nothing to do

    extern __shared__ char smem[];
    const uint32_t smem_base = smem_to_u32(smem);
    const int tid = threadIdx.x;
    const int wid = tid >> 5;        // 0..15
    const int lid = tid & 31;
    const int wm = wid & 3;          // M block of 32
    const int wn = wid >> 2;         // N block of 64
    const int m0 = blockIdx.y * TILE_M;
    const int n0 = blockIdx.x * TILE_N;

    float acc[2][8][4];
#pragma unroll
    for (int i = 0; i < 2; ++i)
#pragma unroll
        for (int j = 0; j < 8; ++j)
#pragma unroll
            for (int k = 0; k < 4; ++k) acc[i][j][k] = 0.f;

    // per-lane constant pieces of the ldmatrix addresses
    const int ar  = wm * 32 + (lid & 15);       // A row (tile-local), +16 for mblk 1
    const int ca  = lid >> 4;                   // A k-chunk bit (0/1)
    const int axr = ar & 7;                     // A swizzle key
    const int bn  = wn * 64 + (lid & 7) + ((lid >> 4) << 3);  // B row base
    const int kb  = (lid >> 3) & 1;             // B k-chunk bit
    const int bxr = bn & 7;                     // B swizzle key

    auto load_chunk = [&](int c) {
        const int st = c & 3;
        const int s  = c >> 6;
        const int k0 = (c & 63) << 6;
        const __nv_bfloat16* Ab = ((s == 1) ? g_xlo : g_xhi) + (size_t)m0 * IN_DIM + k0;
        const __nv_bfloat16* Bb = ((s == 2) ? g_wlo : g_whi) + (size_t)n0 * IN_DIM + k0;
        const uint32_t sa = smem_base + st * STAGE_BYTES;
        const uint32_t sb = sa + A_BYTES;
        // A: 128 rows x 8 x 16B = 1024 ops -> 2/thread
#pragma unroll
        for (int it = 0; it < 2; ++it) {
            int i = tid + it * 512;
            int row = i >> 3, j = i & 7;
            uint32_t dst = sa + row * 128 + ((uint32_t)(j ^ (row & 7)) << 4);
            cp_async16(dst, Ab + (size_t)row * IN_DIM + j * 8);
        }
        // B: 256 rows x 8 x 16B = 2048 ops -> 4/thread
#pragma unroll
        for (int it = 0; it < 4; ++it) {
            int i = tid + it * 512;
            int row = i >> 3, j = i & 7;
            uint32_t dst = sb + row * 128 + ((uint32_t)(j ^ (row & 7)) << 4);
            cp_async16(dst, Bb + (size_t)row * IN_DIM + j * 8);
        }
        CP_COMMIT();
    };

    // prologue: 3 stages in flight
    load_chunk(0);
    load_chunk(1);
    load_chunk(2);

    for (int c = 0; c < NCH; ++c) {
        const int rem = NCH - 1 - c;
        if (rem >= 2)      CP_WAIT(2);
        else if (rem == 1) CP_WAIT(1);
        else               CP_WAIT(0);
        __syncthreads();
        if (c + 3 < NCH) load_chunk(c + 3);

        const uint32_t sa = smem_base + (c & 3) * STAGE_BYTES;
        const uint32_t sb = sa + A_BYTES;

#pragma unroll
        for (int s = 0; s < 4; ++s) {
            uint32_t a[2][4];
#pragma unroll
            for (int mb = 0; mb < 2; ++mb) {
                uint32_t addr = sa + (ar + mb * 16) * 128
                              + ((uint32_t)(((s << 1) + ca) ^ axr) << 4);
                ldsm_x4(a[mb], addr);
            }
#pragma unroll
            for (int nb = 0; nb < 4; ++nb) {
                uint32_t b[4];
                uint32_t addr = sb + (bn + nb * 16) * 128
                              + ((uint32_t)(((s << 1) + kb) ^ bxr) << 4);
                ldsm_x4(b, addr);
#pragma unroll
                for (int mb = 0; mb < 2; ++mb) {
                    mma16816(acc[mb][nb * 2 + 0], a[mb], b + 0);
                    mma16816(acc[mb][nb * 2 + 1], a[mb], b + 2);
                }
            }
        }
    }

    // epilogue: c-frag layout of m16n8k16 -> float2 stores
#pragma unroll
    for (int mb = 0; mb < 2; ++mb) {
        const int r0 = m0 + wm * 32 + mb * 16 + (lid >> 2);
#pragma unroll
        for (int nb8 = 0; nb8 < 8; ++nb8) {
            const int col = n0 + wn * 64 + nb8 * 8 + (lid & 3) * 2;
            float2 v0; v0.x = acc[mb][nb8][0]; v0.y = acc[mb][nb8][1];
            float2 v1; v1.x = acc[mb][nb8][2]; v1.y = acc[mb][nb8][3];
            *(float2*)(out + (size_t)r0 * OUT_DIM + col)       = v0;
            *(float2*)(out + (size_t)(r0 + 8) * OUT_DIM + col) = v1;
        }
    }
}

// ============================================================================
// Host entry
// ============================================================================
extern "C" void kernel_launch(void* const* d_in, const int* in_sizes, int n_in,
                              void* d_out, int out_size) {
    (void)in_sizes; (void)n_in; (void)out_size;
    const float* x      = (const float*)d_in[0];
    const float* W_org  = (const float*)d_in[1];
    const float* q_w    = (const float*)d_in[2];
    const float* p_w    = (const float*)d_in[3];
    const float* lam    = (const float*)d_in[4];
    const float* bq_w   = (const float*)d_in[5];
    const float* bp_w   = (const float*)d_in[6];
    const float* blam   = (const float*)d_in[7];
    float* out = (float*)d_out;

    static int attr_done = 0;
    cudaFuncSetAttribute(gemm_tc_kernel,
                         cudaFuncAttributeMaxDynamicSharedMemorySize, SMEM_TC);
    cudaFuncSetAttribute(gemm_fb_kernel,
                         cudaFuncAttributeMaxDynamicSharedMemorySize, SMEM_FB);
    (void)attr_done;

    probe_kernel<<<1, 1>>>();
    build_aprime_kernel<<<(OUT_DIM * 2 * RANK) / 256, 256>>>(p_w, lam, bp_w, blam);
    fold_w_kernel<<<dim3(IN_DIM / 1024, OUT_DIM / 16), 256>>>(W_org, q_w, bq_w);
    split_x_kernel<<<(int)(((size_t)M_TOTAL * IN_DIM / 4) / 256), 256>>>(
        (const float4*)x);

    dim3 grid(OUT_DIM / TILE_N, M_TOTAL / TILE_M);
    gemm_tc_kernel<<<grid, 256, SMEM_TC>>>(out);   // no-op on plain pass
    gemm_fb_kernel<<<grid, 512, SMEM_FB>>>(out);   // no-op when tcgen05 live
}

// round 4
// speedup vs baseline: 1.1371x; 1.1371x over previous
#include <cuda_runtime.h>
#include <cuda_bf16.h>
#include <cstdint>

// ============================================================================
// Feature gate: tcgen05 only exists on the sm_103a (arch-accelerated) pass.
// Round-3 timing proves the a-pass is what executes (effective 1300 TF/s is
// impossible on mma.sync). Fallback kept as safety, gated by g_has_tc.
// ============================================================================
#if defined(__CUDA_ARCH__) && defined(__CUDA_ARCH_FEAT_SM103_ALL)
#define HAS_TC 1
#else
#define HAS_TC 0
#endif

// ============================================================================
// Problem constants
// ============================================================================
#define IN_DIM   4096
#define OUT_DIM  4096
#define RANK     64
#define M_TOTAL  16384            // 4 * 4096 rows of x

#define NKG      64               // K groups of 64 bf16 columns

// ---- tcgen05 path tiling: 256x256 CTA tile, operand-sharing schedule ----
#define TILE_M   256
#define TILE_N   256
#define TILE_BYTES 32768          // 256 rows x 128 B
#define NSA      3                // A-ring slots
#define NSB      4                // B-ring slots
#define SMEM_CTRL 1024
#define SMEM_A0  SMEM_CTRL
#define SMEM_B0  (SMEM_CTRL + NSA * TILE_BYTES)
#define SMEM_TC  (SMEM_CTRL + (NSA + NSB) * TILE_BYTES)   // 230400 <= 232448
#define GEMM_IDESC 0x8400490u     // f16-kind, bf16xbf16->f32, M=128, N=256

// ---- fallback path tiling (unchanged from round 3) ----
#define FB_TM    128
#define FB_TN    256
#define FB_A_BYTES (FB_TM * 128)
#define FB_B_BYTES (FB_TN * 128)
#define FB_STAGE   (FB_A_BYTES + FB_B_BYTES)
#define SMEM_FB  (4 * FB_STAGE)
#define FB_NCH   (3 * NKG)

// ============================================================================
// Device scratch (static globals — no runtime allocation)
// ============================================================================
__device__ __align__(256) __nv_bfloat16 g_xhi[(size_t)M_TOTAL * IN_DIM];
__device__ __align__(256) __nv_bfloat16 g_xlo[(size_t)M_TOTAL * IN_DIM];
__device__ __align__(256) __nv_bfloat16 g_whi[(size_t)OUT_DIM * IN_DIM];
__device__ __align__(256) __nv_bfloat16 g_wlo[(size_t)OUT_DIM * IN_DIM];
__device__ __align__(256) float         g_aprime[OUT_DIM * 2 * RANK];
__device__ int g_has_tc;

// ============================================================================
// Common PTX helpers (legal on plain sm_103)
// ============================================================================
__device__ __forceinline__ uint32_t smem_to_u32(const void* p) {
    uint32_t a;
    asm("{ .reg .u64 t; cvta.to.shared.u64 t, %1; cvt.u32.u64 %0, t; }"
        : "=r"(a) : "l"(p));
    return a;
}

__device__ __forceinline__ void cp_async16(uint32_t dst, const void* src) {
    asm volatile("cp.async.cg.shared.global [%0], [%1], 16;"
                 :: "r"(dst), "l"(src));
}
#define CP_COMMIT() asm volatile("cp.async.commit_group;" ::: "memory")
#define CP_WAIT(n)  asm volatile("cp.async.wait_group %0;" :: "n"(n) : "memory")

__device__ __forceinline__ void ldsm_x4(uint32_t* r, uint32_t addr) {
    asm volatile("ldmatrix.sync.aligned.m8n8.x4.shared.b16 {%0,%1,%2,%3}, [%4];"
        : "=r"(r[0]), "=r"(r[1]), "=r"(r[2]), "=r"(r[3]) : "r"(addr));
}

__device__ __forceinline__ void mma16816(float* d, const uint32_t* a,
                                         const uint32_t* b) {
    asm volatile(
        "mma.sync.aligned.m16n8k16.row.col.f32.bf16.bf16.f32 "
        "{%0,%1,%2,%3}, {%4,%5,%6,%7}, {%8,%9}, {%0,%1,%2,%3};"
        : "+f"(d[0]), "+f"(d[1]), "+f"(d[2]), "+f"(d[3])
        : "r"(a[0]), "r"(a[1]), "r"(a[2]), "r"(a[3]), "r"(b[0]), "r"(b[1]));
}

// ============================================================================
// Probe: record whether the loaded SASS is the sm_103a pass
// ============================================================================
__global__ void probe_kernel() { g_has_tc = HAS_TC; }

// ============================================================================
// Kernel A0: A' = [ P*diag(lam) | -P_b*diag(lam_b) ]  (4096 x 128)
// ============================================================================
__global__ void build_aprime_kernel(const float* __restrict__ p_w,
                                    const float* __restrict__ lam,
                                    const float* __restrict__ bp_w,
                                    const float* __restrict__ blam) {
    int idx = blockIdx.x * 256 + threadIdx.x;   // < 4096*128
    int o = idx >> 7;
    int r = idx & 127;
    float v;
    if (r < RANK) v =  p_w[o * RANK + r] * lam[r];
    else          v = -(bp_w[o * RANK + (r - RANK)] * blam[r - RANK]);
    g_aprime[idx] = v;
}

// ============================================================================
// Kernel A1: W_eff = W_org + A' @ [Q ; Q_b], split into bf16 hi/lo
// ============================================================================
__global__ __launch_bounds__(256) void fold_w_kernel(
    const float* __restrict__ W_org,
    const float* __restrict__ q_w,
    const float* __restrict__ base_q_w) {
    __shared__ float sA[16][128];
    const int o0 = blockIdx.y * 16;
    const int i0 = blockIdx.x * 1024;
    const int tid = threadIdx.x;

    for (int t = tid; t < 16 * 128; t += 256)
        sA[t >> 7][t & 127] = g_aprime[(size_t)(o0 + (t >> 7)) * 128 + (t & 127)];
    __syncthreads();

    const int i = i0 + tid * 4;
    float4 acc[16];
#pragma unroll
    for (int oo = 0; oo < 16; ++oo)
        acc[oo] = *(const float4*)(W_org + (size_t)(o0 + oo) * IN_DIM + i);

#pragma unroll 4
    for (int r = 0; r < RANK; ++r) {
        float4 b = *(const float4*)(q_w + (size_t)r * IN_DIM + i);
#pragma unroll
        for (int oo = 0; oo < 16; ++oo) {
            float s = sA[oo][r];
            acc[oo].x += s * b.x; acc[oo].y += s * b.y;
            acc[oo].z += s * b.z; acc[oo].w += s * b.w;
        }
    }
#pragma unroll 4
    for (int r = 0; r < RANK; ++r) {
        float4 b = *(const float4*)(base_q_w + (size_t)r * IN_DIM + i);
#pragma unroll
        for (int oo = 0; oo < 16; ++oo) {
            float s = sA[oo][RANK + r];
            acc[oo].x += s * b.x; acc[oo].y += s * b.y;
            acc[oo].z += s * b.z; acc[oo].w += s * b.w;
        }
    }

#pragma unroll
    for (int oo = 0; oo < 16; ++oo) {
        size_t base = (size_t)(o0 + oo) * IN_DIM + i;
        float v[4] = {acc[oo].x, acc[oo].y, acc[oo].z, acc[oo].w};
        __nv_bfloat16 h[4], l[4];
#pragma unroll
        for (int k = 0; k < 4; ++k) {
            h[k] = __float2bfloat16(v[k]);
            l[k] = __float2bfloat16(v[k] - __bfloat162float(h[k]));
        }
        __nv_bfloat162* ph = (__nv_bfloat162*)(g_whi + base);
        __nv_bfloat162* pl = (__nv_bfloat162*)(g_wlo + base);
        __nv_bfloat162 h01; h01.x = h[0]; h01.y = h[1];
        __nv_bfloat162 h23; h23.x = h[2]; h23.y = h[3];
        __nv_bfloat162 l01; l01.x = l[0]; l01.y = l[1];
        __nv_bfloat162 l23; l23.x = l[2]; l23.y = l[3];
        ph[0] = h01; ph[1] = h23;
        pl[0] = l01; pl[1] = l23;
    }
}

// ============================================================================
// Kernel B: split x into bf16 hi/lo
// ============================================================================
__global__ __launch_bounds__(256) void split_x_kernel(const float4* __restrict__ x) {
    size_t i = (size_t)blockIdx.x * 256 + threadIdx.x;  // float4 index
    float4 v = x[i];
    float f[4] = {v.x, v.y, v.z, v.w};
    __nv_bfloat16 h[4], l[4];
#pragma unroll
    for (int k = 0; k < 4; ++k) {
        h[k] = __float2bfloat16(f[k]);
        l[k] = __float2bfloat16(f[k] - __bfloat162float(h[k]));
    }
    __nv_bfloat162 h01; h01.x = h[0]; h01.y = h[1];
    __nv_bfloat162 h23; h23.x = h[2]; h23.y = h[3];
    __nv_bfloat162 l01; l01.x = l[0]; l01.y = l[1];
    __nv_bfloat162 l23; l23.x = l[2]; l23.y = l[3];
    ((__nv_bfloat162*)g_xhi)[i * 2 + 0] = h01;
    ((__nv_bfloat162*)g_xhi)[i * 2 + 1] = h23;
    ((__nv_bfloat162*)g_xlo)[i * 2 + 0] = l01;
    ((__nv_bfloat162*)g_xlo)[i * 2 + 1] = l23;
}

// ============================================================================
// tcgen05-only helpers (emitted only on the sm_103a pass)
// ============================================================================
#if HAS_TC
__device__ __forceinline__ uint32_t elect_one_pred() {
    uint32_t pred;
    asm volatile(
        "{\n\t.reg .pred p;\n\t"
        "elect.sync _|p, 0xFFFFFFFF;\n\t"
        "selp.b32 %0, 1, 0, p;\n\t}"
        : "=r"(pred));
    return pred;
}

#define TCGEN05_ALLOC(smem_addr, nCols) \
    asm volatile("tcgen05.alloc.cta_group::1.sync.aligned.shared::cta.b32 [%0], %1;" \
        :: "r"((uint32_t)(smem_addr)), "r"((uint32_t)(nCols)) : "memory")
#define TCGEN05_DEALLOC(tmem_addr, nCols) \
    asm volatile("tcgen05.dealloc.cta_group::1.sync.aligned.b32 %0, %1;" \
        :: "r"(tmem_addr), "r"((uint32_t)(nCols)))
#define TCGEN05_RELINQ() \
    asm volatile("tcgen05.relinquish_alloc_permit.cta_group::1.sync.aligned;")
#define TCGEN05_COMMIT(mbar) \
    asm volatile("tcgen05.commit.cta_group::1.mbarrier::arrive::one.shared::cluster.b64 [%0];" \
        :: "r"((uint32_t)(mbar)) : "memory")
#define TCGEN05_FENCE_AFTER() \
    asm volatile("tcgen05.fence::after_thread_sync;" ::: "memory")
#define TCGEN05_FENCE_BEFORE() \
    asm volatile("tcgen05.fence::before_thread_sync;" ::: "memory")
#define TCGEN05_WAIT_LD() \
    asm volatile("tcgen05.wait::ld.sync.aligned;" ::: "memory")
#define FENCE_PROXY_ASYNC_SHARED_CTA() \
    asm volatile("fence.proxy.async.shared::cta;" ::: "memory")
#define MBARRIER_INIT(mbar, cnt) \
    asm volatile("mbarrier.init.shared.b64 [%0], %1;" \
        :: "r"((uint32_t)(mbar)), "r"((uint32_t)(cnt)) : "memory")
#define MBARRIER_WAIT_PARITY(mbar, parity) do { \
    uint32_t _m = (uint32_t)(mbar); uint32_t _p = (uint32_t)(parity); uint32_t _d; \
    asm volatile("{\n\t.reg .pred p;\n\t" \
        "mbarrier.try_wait.parity.acquire.cta.shared::cta.b64 p, [%1], %2;\n\t" \
        "selp.b32 %0, 1, 0, p;\n\t}" : "=r"(_d) : "r"(_m), "r"(_p) : "memory"); \
    if (!_d) { \
        asm volatile("{\n\t.reg .pred P1;\n\t" \
            "WAIT_LOOP_%=:\n\t" \
            "mbarrier.try_wait.parity.acquire.cta.shared::cta.b64 P1, [%0], %1, 0x989680;\n\t" \
            "@P1 bra.uni WAIT_DONE_%=;\n\t" \
            "bra.uni WAIT_LOOP_%=;\n\t" \
            "WAIT_DONE_%=:\n\t}" :: "r"(_m), "r"(_p) : "memory"); \
    } \
} while (0)
#define TCGEN05_LD_32X32B_X32(r, tmem_addr) \
    asm volatile( \
        "tcgen05.ld.sync.aligned.32x32b.x32.b32 " \
        "{%0, %1, %2, %3, %4, %5, %6, %7, " \
        " %8, %9, %10, %11, %12, %13, %14, %15, " \
        " %16, %17, %18, %19, %20, %21, %22, %23, " \
        " %24, %25, %26, %27, %28, %29, %30, %31}, [%32];" \
        : "=r"((r)[0]),  "=r"((r)[1]),  "=r"((r)[2]),  "=r"((r)[3]), \
          "=r"((r)[4]),  "=r"((r)[5]),  "=r"((r)[6]),  "=r"((r)[7]), \
          "=r"((r)[8]),  "=r"((r)[9]),  "=r"((r)[10]), "=r"((r)[11]), \
          "=r"((r)[12]), "=r"((r)[13]), "=r"((r)[14]), "=r"((r)[15]), \
          "=r"((r)[16]), "=r"((r)[17]), "=r"((r)[18]), "=r"((r)[19]), \
          "=r"((r)[20]), "=r"((r)[21]), "=r"((r)[22]), "=r"((r)[23]), \
          "=r"((r)[24]), "=r"((r)[25]), "=r"((r)[26]), "=r"((r)[27]), \
          "=r"((r)[28]), "=r"((r)[29]), "=r"((r)[30]), "=r"((r)[31]) \
        : "r"(tmem_addr))

static constexpr uint64_t SMEM_DESC_BASE_SW128 =
      (uint64_t(2)  << 61) | (uint64_t(1) << 46)
    | (uint64_t(64) << 32) | (uint64_t(1) << 16);
#define MAKE_SMEM_DESC(base_addr) \
    (SMEM_DESC_BASE_SW128 | ((uint64_t)((base_addr) >> 4) & 0x3FFF))

__device__ __forceinline__ void mma_f16_ss(uint32_t d_tmem, uint64_t a_desc,
                                           uint64_t b_desc, uint32_t idesc,
                                           uint32_t enable_d) {
    asm volatile(
        "{\n\t.reg .pred p;\n\t"
        "setp.ne.u32 p, %4, 0;\n\t"
        "tcgen05.mma.cta_group::1.kind::f16 [%0], %1, %2, %3, {%5, %5, %5, %5}, p;\n\t"
        "}"
        :: "r"(d_tmem), "l"(a_desc), "l"(b_desc), "r"(idesc),
           "r"(enable_d), "r"(0u)
        : "memory");
}
#endif // HAS_TC

// ============================================================================
// GEMM (tcgen05 path): 256x256 CTA tile, operand-sharing schedule.
// Per K-group g (64 bf16 cols): load 4 tiles (Ahi, Alo, Bhi, Blo; 32 KB each),
// run 3 products P(3g)=Ahi*Bhi, P(3g+1)=Ahi*Blo, P(3g+2)=Alo*Bhi, all
// accumulating into one 256x256 fp32 TMEM accumulator (two M=128 halves at
// TMEM cols 0 and 256). A-ring 3 slots, B-ring 4 slots; per-product mbarrier
// commits gate slot reuse; cp.async groups kept uniform with empty commits.
// ============================================================================
__global__ __launch_bounds__(256, 1)
void gemm_tc_kernel(float* __restrict__ out) {
#if HAS_TC
    extern __shared__ char smem[];
    const uint32_t smem_base = smem_to_u32(smem);
    const int tid = threadIdx.x;
    const int wid = tid >> 5;
    const int lid = tid & 31;
    const int m0 = blockIdx.y * TILE_M;
    const int n0 = blockIdx.x * TILE_N;

    if (wid == 0) {
        TCGEN05_ALLOC(smem_base + 64, 512);
        TCGEN05_RELINQ();
    }
    if (tid == 0) {
#pragma unroll
        for (int s = 0; s < 4; ++s) MBARRIER_INIT(smem_base + 8 * s, 1);
    }
    __syncthreads();

    uint32_t tmem;
    asm volatile("ld.shared.b32 %0, [%1];" : "=r"(tmem) : "r"(smem_base + 64));

    const __nv_bfloat16* Ahi = g_xhi + (size_t)m0 * IN_DIM;
    const __nv_bfloat16* Alo = g_xlo + (size_t)m0 * IN_DIM;
    const __nv_bfloat16* Bhi = g_whi + (size_t)n0 * IN_DIM;
    const __nv_bfloat16* Blo = g_wlo + (size_t)n0 * IN_DIM;

    // 256-row x 128B tile loader: 2048 cp.async16 ops, 8 per thread
    auto load_tile = [&](const __nv_bfloat16* g, uint32_t sbase) {
#pragma unroll
        for (int it = 0; it < 8; ++it) {
            int i = tid + it * 256;
            int row = i >> 3, j = i & 7;
            uint32_t off = (uint32_t)(row * 128 + j * 16);
            uint32_t dst = sbase + (off ^ ((off >> 3) & 0x70));
            cp_async16(dst, g + (size_t)row * IN_DIM + j * 8);
        }
    };
    auto aslot = [&](int j) {
        return smem_base + SMEM_A0 + (uint32_t)(j % NSA) * TILE_BYTES;
    };
    auto bslot = [&](int j) {
        return smem_base + SMEM_B0 + (uint32_t)(j % NSB) * TILE_BYTES;
    };

    // ---- prologue: 4 commit groups matching steady-state pattern ----------
    load_tile(Blo, bslot(1));                              CP_COMMIT(); // Ga(-2)
    load_tile(Ahi, aslot(0)); load_tile(Bhi, bslot(0));    CP_COMMIT(); // Gb(-2)
    load_tile(Alo, aslot(1)); load_tile(Blo + 64, bslot(3)); CP_COMMIT(); // Ga(-1)
    load_tile(Ahi + 64, aslot(2)); load_tile(Bhi + 64, bslot(2)); CP_COMMIT(); // Gb(-1)

    for (int g = 0; g < NKG; ++g) {
        // -- have Ahi(g), Bhi(g), Blo(g): products P(3g), P(3g+1) -----------
        CP_WAIT(2);
        FENCE_PROXY_ASYNC_SHARED_CTA();
        __syncthreads();
        if (wid == 0) {
            if (elect_one_pred()) {
                const uint32_t sa = aslot(2 * g);
                const uint64_t ah0 = MAKE_SMEM_DESC(sa);
                const uint64_t ah1 = MAKE_SMEM_DESC(sa + 16384);
                const uint64_t bh  = MAKE_SMEM_DESC(bslot(2 * g));
                const uint64_t bl  = MAKE_SMEM_DESC(bslot(2 * g + 1));
#pragma unroll
                for (int k = 0; k < 4; ++k) {
                    uint32_t en = (g > 0 || k > 0) ? 1u : 0u;
                    mma_f16_ss(tmem,       ah0 + k * 2, bh + k * 2, GEMM_IDESC, en);
                    mma_f16_ss(tmem + 256, ah1 + k * 2, bh + k * 2, GEMM_IDESC, en);
                }
                TCGEN05_COMMIT(smem_base + 8 * ((3 * g) & 3));
#pragma unroll
                for (int k = 0; k < 4; ++k) {
                    mma_f16_ss(tmem,       ah0 + k * 2, bl + k * 2, GEMM_IDESC, 1u);
                    mma_f16_ss(tmem + 256, ah1 + k * 2, bl + k * 2, GEMM_IDESC, 1u);
                }
                TCGEN05_COMMIT(smem_base + 8 * ((3 * g + 1) & 3));
            }
        }
        // -- have Alo(g): product P(3g+2) -----------------------------------
        CP_WAIT(1);
        FENCE_PROXY_ASYNC_SHARED_CTA();
        __syncthreads();
        if (wid == 0) {
            if (elect_one_pred()) {
                const uint32_t sal = aslot(2 * g + 1);
                const uint64_t al0 = MAKE_SMEM_DESC(sal);
                const uint64_t al1 = MAKE_SMEM_DESC(sal + 16384);
                const uint64_t bh  = MAKE_SMEM_DESC(bslot(2 * g));
#pragma unroll
                for (int k = 0; k < 4; ++k) {
                    mma_f16_ss(tmem,       al0 + k * 2, bh + k * 2, GEMM_IDESC, 1u);
                    mma_f16_ss(tmem + 256, al1 + k * 2, bh + k * 2, GEMM_IDESC, 1u);
                }
                TCGEN05_COMMIT(smem_base + 8 * ((3 * g + 2) & 3));
            }
        }
        // -- P(3g+1) done -> slots of Ahi(g) & Blo(g) free: issue Ga(g) ------
        {
            const int c = 3 * g + 1;
            MBARRIER_WAIT_PARITY(smem_base + 8 * (c & 3), (c >> 2) & 1);
        }
        if (g + 1 < NKG) load_tile(Alo + (size_t)(g + 1) * 64, aslot(2 * g + 3));
        if (g + 2 < NKG) load_tile(Blo + (size_t)(g + 2) * 64, bslot(2 * g + 5));
        CP_COMMIT();   // Ga(g) (possibly empty at tail)
        // -- P(3g+2) done -> slots of Alo(g) & Bhi(g) free: issue Gb(g) ------
        {
            const int c = 3 * g + 2;
            MBARRIER_WAIT_PARITY(smem_base + 8 * (c & 3), (c >> 2) & 1);
        }
        if (g + 2 < NKG) {
            load_tile(Ahi + (size_t)(g + 2) * 64, aslot(2 * g + 4));
            load_tile(Bhi + (size_t)(g + 2) * 64, bslot(2 * g + 4));
        }
        CP_COMMIT();   // Gb(g) (possibly empty at tail)
    }
    TCGEN05_FENCE_AFTER();

    // ---- epilogue: warps 0-3 -> M-half 0 (TMEM cols 0..255),
    //                warps 4-7 -> M-half 1 (TMEM cols 256..511)
    {
        const int half = wid >> 2;
        const int sub  = wid & 3;
        const uint32_t lane_off = ((uint32_t)sub) << 21;
        const int m = m0 + half * 128 + sub * 32 + lid;
        float* orow = out + (size_t)m * OUT_DIM + n0;
#pragma unroll
        for (int cc = 0; cc < 8; ++cc) {
            uint32_t r[32];
            TCGEN05_LD_32X32B_X32(
                r, tmem + lane_off + (uint32_t)(half * 256 + cc * 32));
            TCGEN05_WAIT_LD();
            float* dst = orow + cc * 32;
#pragma unroll
            for (int q = 0; q < 8; ++q) {
                float4 v;
                v.x = __uint_as_float(r[4 * q + 0]);
                v.y = __uint_as_float(r[4 * q + 1]);
                v.z = __uint_as_float(r[4 * q + 2]);
                v.w = __uint_as_float(r[4 * q + 3]);
                ((float4*)dst)[q] = v;
            }
        }
        TCGEN05_FENCE_BEFORE();
    }

    __syncthreads();
    if (wid == 0) TCGEN05_DEALLOC(tmem, 512);
#else
    (void)out;   // empty on plain sm_103 pass; fallback kernel does the work
#endif
}

// ============================================================================
// GEMM (mma.sync fallback) — unchanged round-3 structure, own 128x256 grid.
// ============================================================================
__global__ __launch_bounds__(512, 1)
void gemm_fb_kernel(float* __restrict__ out) {
    if (g_has_tc) return;   // tcgen05 path is live; nothing to do

    extern __shared__ char smem[];
    const uint32_t smem_base = smem_to_u32(smem);
    const int tid = threadIdx.x;
    const int wid = tid >> 5;        // 0..15
    const int lid = tid & 31;
    const int wm = wid & 3;          // M block of 32
    const int wn = wid >> 2;         // N block of 64
    const int m0 = blockIdx.y * FB_TM;
    const int n0 = blockIdx.x * FB_TN;

    float acc[2][8][4];
#pragma unroll
    for (int i = 0; i < 2; ++i)
#pragma unroll
        for (int j = 0; j < 8; ++j)
#pragma unroll
            for (int k = 0; k < 4; ++k) acc[i][j][k] = 0.f;

    const int ar  = wm * 32 + (lid & 15);
    const int ca  = lid >> 4;
    const int axr = ar & 7;
    const int bn  = wn * 64 + (lid & 7) + ((lid >> 4) << 3);
    const int kb  = (lid >> 3) & 1;
    const int bxr = bn & 7;

    auto load_chunk = [&](int c) {
        const int st = c & 3;
        const int s  = c >> 6;
        const int k0 = (c & 63) << 6;
        const __nv_bfloat16* Ab = ((s == 1) ? g_xlo : g_xhi) + (size_t)m0 * IN_DIM + k0;
        const __nv_bfloat16* Bb = ((s == 2) ? g_wlo : g_whi) + (size_t)n0 * IN_DIM + k0;
        const uint32_t sa = smem_base + st * FB_STAGE;
        const uint32_t sb = sa + FB_A_BYTES;
#pragma unroll
        for (int it = 0; it < 2; ++it) {
            int i = tid + it * 512;
            int row = i >> 3, j = i & 7;
            uint32_t dst = sa + row * 128 + ((uint32_t)(j ^ (row & 7)) << 4);
            cp_async16(dst, Ab + (size_t)row * IN_DIM + j * 8);
        }
#pragma unroll
        for (int it = 0; it < 4; ++it) {
            int i = tid + it * 512;
            int row = i >> 3, j = i & 7;
            uint32_t dst = sb + row * 128 + ((uint32_t)(j ^ (row & 7)) << 4);
            cp_async16(dst, Bb + (size_t)row * IN_DIM + j * 8);
        }
        CP_COMMIT();
    };

    load_chunk(0);
    load_chunk(1);
    load_chunk(2);

    for (int c = 0; c < FB_NCH; ++c) {
        const int rem = FB_NCH - 1 - c;
        if (rem >= 2)      CP_WAIT(2);
        else if (rem == 1) CP_WAIT(1);
        else               CP_WAIT(0);
        __syncthreads();
        if (c + 3 < FB_NCH) load_chunk(c + 3);

        const uint32_t sa = smem_base + (c & 3) * FB_STAGE;
        const uint32_t sb = sa + FB_A_BYTES;

#pragma unroll
        for (int s = 0; s < 4; ++s) {
            uint32_t a[2][4];
#pragma unroll
            for (int mb = 0; mb < 2; ++mb) {
                uint32_t addr = sa + (ar + mb * 16) * 128
                              + ((uint32_t)(((s << 1) + ca) ^ axr) << 4);
                ldsm_x4(a[mb], addr);
            }
#pragma unroll
            for (int nb = 0; nb < 4; ++nb) {
                uint32_t b[4];
                uint32_t addr = sb + (bn + nb * 16) * 128
                              + ((uint32_t)(((s << 1) + kb) ^ bxr) << 4);
                ldsm_x4(b, addr);
#pragma unroll
                for (int mb = 0; mb < 2; ++mb) {
                    mma16816(acc[mb][nb * 2 + 0], a[mb], b + 0);
                    mma16816(acc[mb][nb * 2 + 1], a[mb], b + 2);
                }
            }
        }
    }

#pragma unroll
    for (int mb = 0; mb < 2; ++mb) {
        const int r0 = m0 + wm * 32 + mb * 16 + (lid >> 2);
#pragma unroll
        for (int nb8 = 0; nb8 < 8; ++nb8) {
            const int col = n0 + wn * 64 + nb8 * 8 + (lid & 3) * 2;
            float2 v0; v0.x = acc[mb][nb8][0]; v0.y = acc[mb][nb8][1];
            float2 v1; v1.x = acc[mb][nb8][2]; v1.y = acc[mb][nb8][3];
            *(float2*)(out + (size_t)r0 * OUT_DIM + col)       = v0;
            *(float2*)(out + (size_t)(r0 + 8) * OUT_DIM + col) = v1;
        }
    }
}

// ============================================================================
// Host entry
// ============================================================================
extern "C" void kernel_launch(void* const* d_in, const int* in_sizes, int n_in,
                              void* d_out, int out_size) {
    (void)in_sizes; (void)n_in; (void)out_size;
    const float* x      = (const float*)d_in[0];
    const float* W_org  = (const float*)d_in[1];
    const float* q_w    = (const float*)d_in[2];
    const float* p_w    = (const float*)d_in[3];
    const float* lam    = (const float*)d_in[4];
    const float* bq_w   = (const float*)d_in[5];
    const float* bp_w   = (const float*)d_in[6];
    const float* blam   = (const float*)d_in[7];
    float* out = (float*)d_out;

    cudaFuncSetAttribute(gemm_tc_kernel,
                         cudaFuncAttributeMaxDynamicSharedMemorySize, SMEM_TC);
    cudaFuncSetAttribute(gemm_fb_kernel,
                         cudaFuncAttributeMaxDynamicSharedMemorySize, SMEM_FB);

    probe_kernel<<<1, 1>>>();
    build_aprime_kernel<<<(OUT_DIM * 2 * RANK) / 256, 256>>>(p_w, lam, bp_w, blam);
    fold_w_kernel<<<dim3(IN_DIM / 1024, OUT_DIM / 16), 256>>>(W_org, q_w, bq_w);
    split_x_kernel<<<(int)(((size_t)M_TOTAL * IN_DIM / 4) / 256), 256>>>(
        (const float4*)x);

    gemm_tc_kernel<<<dim3(OUT_DIM / TILE_N, M_TOTAL / TILE_M), 256, SMEM_TC>>>(out);
    gemm_fb_kernel<<<dim3(OUT_DIM / FB_TN, M_TOTAL / FB_TM), 512, SMEM_FB>>>(out);
}

// round 5
// speedup vs baseline: 1.2707x; 1.1175x over previous
#include <cuda_runtime.h>
#include <cuda.h>
#include <cuda_bf16.h>
#include <cstdint>

// ============================================================================
// Feature gate: tcgen05 exists only on the sm_103a pass. Round-3/4 timing
// proves the a-pass executes. mma.sync fallback retained, gated by g_has_tc.
// ============================================================================
#if defined(__CUDA_ARCH__) && defined(__CUDA_ARCH_FEAT_SM103_ALL)
#define HAS_TC 1
#else
#define HAS_TC 0
#endif

// ============================================================================
// Problem constants
// ============================================================================
#define IN_DIM   4096
#define OUT_DIM  4096
#define RANK     64
#define M_TOTAL  16384            // 4 * 4096 rows of x

#define NKG      64               // K groups of 64 bf16 columns

// ---- tcgen05 path: 256x256 CTA tile, operand-sharing, TMA warp-specialized
#define TILE_M   256
#define TILE_N   256
#define TILE_BYTES 32768          // 256 rows x 128 B
#define NSA      3                // A-ring slots
#define NSB      4                // B-ring slots
#define SMEM_CTRL 1024
#define SMEM_A0  SMEM_CTRL
#define SMEM_B0  (SMEM_CTRL + NSA * TILE_BYTES)
#define SMEM_TC  (SMEM_CTRL + (NSA + NSB) * TILE_BYTES)   // 230400
#define GEMM_IDESC 0x8400490u     // f16-kind, bf16xbf16->f32, M=128, N=256

// ---- fallback path tiling ----
#define FB_TM    128
#define FB_TN    256
#define FB_A_BYTES (FB_TM * 128)
#define FB_B_BYTES (FB_TN * 128)
#define FB_STAGE   (FB_A_BYTES + FB_B_BYTES)
#define SMEM_FB  (4 * FB_STAGE)
#define FB_NCH   (3 * NKG)

// ============================================================================
// Device scratch (static globals — no runtime allocation)
// ============================================================================
__device__ __align__(256) __nv_bfloat16 g_xhi[(size_t)M_TOTAL * IN_DIM];
__device__ __align__(256) __nv_bfloat16 g_xlo[(size_t)M_TOTAL * IN_DIM];
__device__ __align__(256) __nv_bfloat16 g_whi[(size_t)OUT_DIM * IN_DIM];
__device__ __align__(256) __nv_bfloat16 g_wlo[(size_t)OUT_DIM * IN_DIM];
__device__ __align__(256) float         g_aprime[OUT_DIM * 2 * RANK];
__device__ int g_has_tc;

// ============================================================================
// Common PTX helpers
// ============================================================================
__device__ __forceinline__ uint32_t smem_to_u32(const void* p) {
    uint32_t a;
    asm("{ .reg .u64 t; cvta.to.shared.u64 t, %1; cvt.u32.u64 %0, t; }"
        : "=r"(a) : "l"(p));
    return a;
}

__device__ __forceinline__ void cp_async16(uint32_t dst, const void* src) {
    asm volatile("cp.async.cg.shared.global [%0], [%1], 16;"
                 :: "r"(dst), "l"(src));
}
#define CP_COMMIT() asm volatile("cp.async.commit_group;" ::: "memory")
#define CP_WAIT(n)  asm volatile("cp.async.wait_group %0;" :: "n"(n) : "memory")

__device__ __forceinline__ void ldsm_x4(uint32_t* r, uint32_t addr) {
    asm volatile("ldmatrix.sync.aligned.m8n8.x4.shared.b16 {%0,%1,%2,%3}, [%4];"
        : "=r"(r[0]), "=r"(r[1]), "=r"(r[2]), "=r"(r[3]) : "r"(addr));
}

__device__ __forceinline__ void mma16816(float* d, const uint32_t* a,
                                         const uint32_t* b) {
    asm volatile(
        "mma.sync.aligned.m16n8k16.row.col.f32.bf16.bf16.f32 "
        "{%0,%1,%2,%3}, {%4,%5,%6,%7}, {%8,%9}, {%0,%1,%2,%3};"
        : "+f"(d[0]), "+f"(d[1]), "+f"(d[2]), "+f"(d[3])
        : "r"(a[0]), "r"(a[1]), "r"(a[2]), "r"(a[3]), "r"(b[0]), "r"(b[1]));
}

#define MBARRIER_INIT(mbar, cnt) \
    asm volatile("mbarrier.init.shared.b64 [%0], %1;" \
        :: "r"((uint32_t)(mbar)), "r"((uint32_t)(cnt)) : "memory")
#define MBARRIER_EXPECT_TX(mbar, bytes) \
    asm volatile("mbarrier.arrive.expect_tx.shared.b64 _, [%0], %1;" \
        :: "r"((uint32_t)(mbar)), "r"((uint32_t)(bytes)) : "memory")
#define MBARRIER_WAIT_PARITY(mbar, parity) do { \
    uint32_t _m = (uint32_t)(mbar); uint32_t _p = (uint32_t)(parity); uint32_t _d; \
    asm volatile("{\n\t.reg .pred p;\n\t" \
        "mbarrier.try_wait.parity.acquire.cta.shared::cta.b64 p, [%1], %2;\n\t" \
        "selp.b32 %0, 1, 0, p;\n\t}" : "=r"(_d) : "r"(_m), "r"(_p) : "memory"); \
    if (!_d) { \
        asm volatile("{\n\t.reg .pred P1;\n\t" \
            "WAIT_LOOP_%=:\n\t" \
            "mbarrier.try_wait.parity.acquire.cta.shared::cta.b64 P1, [%0], %1, 0x989680;\n\t" \
            "@P1 bra.uni WAIT_DONE_%=;\n\t" \
            "bra.uni WAIT_LOOP_%=;\n\t" \
            "WAIT_DONE_%=:\n\t}" :: "r"(_m), "r"(_p) : "memory"); \
    } \
} while (0)

// TMA 2D load: global->shared::cta, mbarrier complete_tx (legal on plain sm103)
__device__ __forceinline__ void tma_2d(const CUtensorMap* map, uint32_t dst,
                                       int cx, int cy, uint32_t mbar) {
    asm volatile(
        "cp.async.bulk.tensor.2d.shared::cta.global.tile.mbarrier::complete_tx::bytes "
        "[%0], [%1, {%2, %3}], [%4];"
        :: "r"(dst), "l"(map), "r"(cx), "r"(cy), "r"(mbar) : "memory");
}

// ============================================================================
// Probe
// ============================================================================
__global__ void probe_kernel() { g_has_tc = HAS_TC; }

// ============================================================================
// Kernel A0: A' = [ P*diag(lam) | -P_b*diag(lam_b) ]  (4096 x 128)
// ============================================================================
__global__ void build_aprime_kernel(const float* __restrict__ p_w,
                                    const float* __restrict__ lam,
                                    const float* __restrict__ bp_w,
                                    const float* __restrict__ blam) {
    int idx = blockIdx.x * 256 + threadIdx.x;
    int o = idx >> 7;
    int r = idx & 127;
    float v;
    if (r < RANK) v =  p_w[o * RANK + r] * lam[r];
    else          v = -(bp_w[o * RANK + (r - RANK)] * blam[r - RANK]);
    g_aprime[idx] = v;
}

// ============================================================================
// Kernel A1: W_eff = W_org + A' @ [Q ; Q_b], split into bf16 hi/lo
// ============================================================================
__global__ __launch_bounds__(256) void fold_w_kernel(
    const float* __restrict__ W_org,
    const float* __restrict__ q_w,
    const float* __restrict__ base_q_w) {
    __shared__ float sA[16][128];
    const int o0 = blockIdx.y * 16;
    const int i0 = blockIdx.x * 1024;
    const int tid = threadIdx.x;

    for (int t = tid; t < 16 * 128; t += 256)
        sA[t >> 7][t & 127] = g_aprime[(size_t)(o0 + (t >> 7)) * 128 + (t & 127)];
    __syncthreads();

    const int i = i0 + tid * 4;
    float4 acc[16];
#pragma unroll
    for (int oo = 0; oo < 16; ++oo)
        acc[oo] = *(const float4*)(W_org + (size_t)(o0 + oo) * IN_DIM + i);

#pragma unroll 4
    for (int r = 0; r < RANK; ++r) {
        float4 b = *(const float4*)(q_w + (size_t)r * IN_DIM + i);
#pragma unroll
        for (int oo = 0; oo < 16; ++oo) {
            float s = sA[oo][r];
            acc[oo].x += s * b.x; acc[oo].y += s * b.y;
            acc[oo].z += s * b.z; acc[oo].w += s * b.w;
        }
    }
#pragma unroll 4
    for (int r = 0; r < RANK; ++r) {
        float4 b = *(const float4*)(base_q_w + (size_t)r * IN_DIM + i);
#pragma unroll
        for (int oo = 0; oo < 16; ++oo) {
            float s = sA[oo][RANK + r];
            acc[oo].x += s * b.x; acc[oo].y += s * b.y;
            acc[oo].z += s * b.z; acc[oo].w += s * b.w;
        }
    }

#pragma unroll
    for (int oo = 0; oo < 16; ++oo) {
        size_t base = (size_t)(o0 + oo) * IN_DIM + i;
        float v[4] = {acc[oo].x, acc[oo].y, acc[oo].z, acc[oo].w};
        __nv_bfloat16 h[4], l[4];
#pragma unroll
        for (int k = 0; k < 4; ++k) {
            h[k] = __float2bfloat16(v[k]);
            l[k] = __float2bfloat16(v[k] - __bfloat162float(h[k]));
        }
        __nv_bfloat162* ph = (__nv_bfloat162*)(g_whi + base);
        __nv_bfloat162* pl = (__nv_bfloat162*)(g_wlo + base);
        __nv_bfloat162 h01; h01.x = h[0]; h01.y = h[1];
        __nv_bfloat162 h23; h23.x = h[2]; h23.y = h[3];
        __nv_bfloat162 l01; l01.x = l[0]; l01.y = l[1];
        __nv_bfloat162 l23; l23.x = l[2]; l23.y = l[3];
        ph[0] = h01; ph[1] = h23;
        pl[0] = l01; pl[1] = l23;
    }
}

// ============================================================================
// Kernel B: split x into bf16 hi/lo
// ============================================================================
__global__ __launch_bounds__(256) void split_x_kernel(const float4* __restrict__ x) {
    size_t i = (size_t)blockIdx.x * 256 + threadIdx.x;
    float4 v = x[i];
    float f[4] = {v.x, v.y, v.z, v.w};
    __nv_bfloat16 h[4], l[4];
#pragma unroll
    for (int k = 0; k < 4; ++k) {
        h[k] = __float2bfloat16(f[k]);
        l[k] = __float2bfloat16(f[k] - __bfloat162float(h[k]));
    }
    __nv_bfloat162 h01; h01.x = h[0]; h01.y = h[1];
    __nv_bfloat162 h23; h23.x = h[2]; h23.y = h[3];
    __nv_bfloat162 l01; l01.x = l[0]; l01.y = l[1];
    __nv_bfloat162 l23; l23.x = l[2]; l23.y = l[3];
    ((__nv_bfloat162*)g_xhi)[i * 2 + 0] = h01;
    ((__nv_bfloat162*)g_xhi)[i * 2 + 1] = h23;
    ((__nv_bfloat162*)g_xlo)[i * 2 + 0] = l01;
    ((__nv_bfloat162*)g_xlo)[i * 2 + 1] = l23;
}

// ============================================================================
// tcgen05-only helpers
// ============================================================================
#if HAS_TC
#define TCGEN05_ALLOC(smem_addr, nCols) \
    asm volatile("tcgen05.alloc.cta_group::1.sync.aligned.shared::cta.b32 [%0], %1;" \
        :: "r"((uint32_t)(smem_addr)), "r"((uint32_t)(nCols)) : "memory")
#define TCGEN05_DEALLOC(tmem_addr, nCols) \
    asm volatile("tcgen05.dealloc.cta_group::1.sync.aligned.b32 %0, %1;" \
        :: "r"(tmem_addr), "r"((uint32_t)(nCols)))
#define TCGEN05_RELINQ() \
    asm volatile("tcgen05.relinquish_alloc_permit.cta_group::1.sync.aligned;")
#define TCGEN05_COMMIT(mbar) \
    asm volatile("tcgen05.commit.cta_group::1.mbarrier::arrive::one.shared::cluster.b64 [%0];" \
        :: "r"((uint32_t)(mbar)) : "memory")
#define TCGEN05_FENCE_AFTER() \
    asm volatile("tcgen05.fence::after_thread_sync;" ::: "memory")
#define TCGEN05_FENCE_BEFORE() \
    asm volatile("tcgen05.fence::before_thread_sync;" ::: "memory")
#define TCGEN05_WAIT_LD() \
    asm volatile("tcgen05.wait::ld.sync.aligned;" ::: "memory")
#define TCGEN05_LD_32X32B_X32(r, tmem_addr) \
    asm volatile( \
        "tcgen05.ld.sync.aligned.32x32b.x32.b32 " \
        "{%0, %1, %2, %3, %4, %5, %6, %7, " \
        " %8, %9, %10, %11, %12, %13, %14, %15, " \
        " %16, %17, %18, %19, %20, %21, %22, %23, " \
        " %24, %25, %26, %27, %28, %29, %30, %31}, [%32];" \
        : "=r"((r)[0]),  "=r"((r)[1]),  "=r"((r)[2]),  "=r"((r)[3]), \
          "=r"((r)[4]),  "=r"((r)[5]),  "=r"((r)[6]),  "=r"((r)[7]), \
          "=r"((r)[8]),  "=r"((r)[9]),  "=r"((r)[10]), "=r"((r)[11]), \
          "=r"((r)[12]), "=r"((r)[13]), "=r"((r)[14]), "=r"((r)[15]), \
          "=r"((r)[16]), "=r"((r)[17]), "=r"((r)[18]), "=r"((r)[19]), \
          "=r"((r)[20]), "=r"((r)[21]), "=r"((r)[22]), "=r"((r)[23]), \
          "=r"((r)[24]), "=r"((r)[25]), "=r"((r)[26]), "=r"((r)[27]), \
          "=r"((r)[28]), "=r"((r)[29]), "=r"((r)[30]), "=r"((r)[31]) \
        : "r"(tmem_addr))

static constexpr uint64_t SMEM_DESC_BASE_SW128 =
      (uint64_t(2)  << 61) | (uint64_t(1) << 46)
    | (uint64_t(64) << 32) | (uint64_t(1) << 16);
#define MAKE_SMEM_DESC(base_addr) \
    (SMEM_DESC_BASE_SW128 | ((uint64_t)((base_addr) >> 4) & 0x3FFF))

__device__ __forceinline__ void mma_f16_ss(uint32_t d_tmem, uint64_t a_desc,
                                           uint64_t b_desc, uint32_t idesc,
                                           uint32_t enable_d) {
    asm volatile(
        "{\n\t.reg .pred p;\n\t"
        "setp.ne.u32 p, %4, 0;\n\t"
        "tcgen05.mma.cta_group::1.kind::f16 [%0], %1, %2, %3, {%5, %5, %5, %5}, p;\n\t"
        "}"
        :: "r"(d_tmem), "l"(a_desc), "l"(b_desc), "r"(idesc),
           "r"(enable_d), "r"(0u)
        : "memory");
}
#endif // HAS_TC

// ============================================================================
// GEMM (tcgen05 path): warp-specialized TMA pipeline.
//   thread 0  (warp 0): MMA issuer — waits full barriers, issues tcgen05.mma,
//                       frees slots via tcgen05.commit -> empty barriers.
//   thread 32 (warp 1): TMA producer — waits empty barriers, expect_tx + TMA.
//   all 8 warps: epilogue after the done barrier.
// Per group g: tiles Ahi(2g)->A-ring, Alo(2g+1)->A-ring, Bhi(2g)->B-ring,
// Blo(2g+1)->B-ring. Products P0=Ahi*Bhi, P1=Ahi*Blo (frees Ahi,Blo),
// P2=Alo*Bhi (frees Alo,Bhi). fp32 accum in 512 TMEM cols (two M=128 halves).
// ============================================================================
__global__ __launch_bounds__(256, 1)
void gemm_tc_kernel(float* __restrict__ out,
                    const __grid_constant__ CUtensorMap mxhi,
                    const __grid_constant__ CUtensorMap mxlo,
                    const __grid_constant__ CUtensorMap mwhi,
                    const __grid_constant__ CUtensorMap mwlo) {
#if HAS_TC
    extern __shared__ char smem[];
    const uint32_t smem_base = smem_to_u32(smem);
    const int tid = threadIdx.x;
    const int wid = tid >> 5;
    const int lid = tid & 31;
    const int m0 = blockIdx.y * TILE_M;
    const int n0 = blockIdx.x * TILE_N;

    // control block: fullA[3]@0, fullB[4]@24, emptyA[3]@56, emptyB[4]@80,
    // done@112, tmem ptr@128
    const uint32_t MB_FULLA  = smem_base + 0;
    const uint32_t MB_FULLB  = smem_base + 24;
    const uint32_t MB_EMPTYA = smem_base + 56;
    const uint32_t MB_EMPTYB = smem_base + 80;
    const uint32_t MB_DONE   = smem_base + 112;

    if (wid == 0) {
        TCGEN05_ALLOC(smem_base + 128, 512);
        TCGEN05_RELINQ();
    }
    if (tid == 0) {
#pragma unroll
        for (int s = 0; s < NSA; ++s) { MBARRIER_INIT(MB_FULLA + 8 * s, 1);
                                        MBARRIER_INIT(MB_EMPTYA + 8 * s, 1); }
#pragma unroll
        for (int s = 0; s < NSB; ++s) { MBARRIER_INIT(MB_FULLB + 8 * s, 1);
                                        MBARRIER_INIT(MB_EMPTYB + 8 * s, 1); }
        MBARRIER_INIT(MB_DONE, 1);
    }
    __syncthreads();

    uint32_t tmem;
    asm volatile("ld.shared.b32 %0, [%1];" : "=r"(tmem) : "r"(smem_base + 128));

    if (tid == 32) {
        // ---------------- producer: 4 TMA loads per group -------------------
        for (int g = 0; g < NKG; ++g) {
            const int cx = g * 64;
            // Ahi: A-tile j=2g
            {
                const int j = 2 * g, s = j % NSA;
                MBARRIER_WAIT_PARITY(MB_EMPTYA + 8 * s, ((j / NSA) & 1) ^ 1);
                MBARRIER_EXPECT_TX(MB_FULLA + 8 * s, TILE_BYTES);
                tma_2d(&mxhi, smem_base + SMEM_A0 + s * TILE_BYTES,
                       cx, m0, MB_FULLA + 8 * s);
            }
            // Bhi: B-tile j=2g
            {
                const int j = 2 * g, s = j % NSB;
                MBARRIER_WAIT_PARITY(MB_EMPTYB + 8 * s, ((j / NSB) & 1) ^ 1);
                MBARRIER_EXPECT_TX(MB_FULLB + 8 * s, TILE_BYTES);
                tma_2d(&mwhi, smem_base + SMEM_B0 + s * TILE_BYTES,
                       cx, n0, MB_FULLB + 8 * s);
            }
            // Blo: B-tile j=2g+1
            {
                const int j = 2 * g + 1, s = j % NSB;
                MBARRIER_WAIT_PARITY(MB_EMPTYB + 8 * s, ((j / NSB) & 1) ^ 1);
                MBARRIER_EXPECT_TX(MB_FULLB + 8 * s, TILE_BYTES);
                tma_2d(&mwlo, smem_base + SMEM_B0 + s * TILE_BYTES,
                       cx, n0, MB_FULLB + 8 * s);
            }
            // Alo: A-tile j=2g+1
            {
                const int j = 2 * g + 1, s = j % NSA;
                MBARRIER_WAIT_PARITY(MB_EMPTYA + 8 * s, ((j / NSA) & 1) ^ 1);
                MBARRIER_EXPECT_TX(MB_FULLA + 8 * s, TILE_BYTES);
                tma_2d(&mxlo, smem_base + SMEM_A0 + s * TILE_BYTES,
                       cx, m0, MB_FULLA + 8 * s);
            }
        }
    } else if (tid == 0) {
        // ---------------- consumer: MMA issue + slot freeing ----------------
        for (int g = 0; g < NKG; ++g) {
            const int jahi = 2 * g,     sahi = jahi % NSA;
            const int jalo = 2 * g + 1, salo = jalo % NSA;
            const int jbhi = 2 * g,     sbhi = jbhi % NSB;
            const int jblo = 2 * g + 1, sblo = jblo % NSB;

            const uint32_t sa  = smem_base + SMEM_A0 + sahi * TILE_BYTES;
            const uint32_t sal = smem_base + SMEM_A0 + salo * TILE_BYTES;
            const uint64_t ah0 = MAKE_SMEM_DESC(sa);
            const uint64_t ah1 = MAKE_SMEM_DESC(sa + 16384);
            const uint64_t al0 = MAKE_SMEM_DESC(sal);
            const uint64_t al1 = MAKE_SMEM_DESC(sal + 16384);
            const uint64_t bh  = MAKE_SMEM_DESC(smem_base + SMEM_B0 + sbhi * TILE_BYTES);
            const uint64_t bl  = MAKE_SMEM_DESC(smem_base + SMEM_B0 + sblo * TILE_BYTES);

            MBARRIER_WAIT_PARITY(MB_FULLA + 8 * sahi, (jahi / NSA) & 1);
            MBARRIER_WAIT_PARITY(MB_FULLB + 8 * sbhi, (jbhi / NSB) & 1);
            // P0 = Ahi * Bhi
#pragma unroll
            for (int k = 0; k < 4; ++k) {
                uint32_t en = (g > 0 || k > 0) ? 1u : 0u;
                mma_f16_ss(tmem,       ah0 + k * 2, bh + k * 2, GEMM_IDESC, en);
                mma_f16_ss(tmem + 256, ah1 + k * 2, bh + k * 2, GEMM_IDESC, en);
            }
            MBARRIER_WAIT_PARITY(MB_FULLB + 8 * sblo, (jblo / NSB) & 1);
            // P1 = Ahi * Blo   (last use of Ahi, Blo)
#pragma unroll
            for (int k = 0; k < 4; ++k) {
                mma_f16_ss(tmem,       ah0 + k * 2, bl + k * 2, GEMM_IDESC, 1u);
                mma_f16_ss(tmem + 256, ah1 + k * 2, bl + k * 2, GEMM_IDESC, 1u);
            }
            TCGEN05_COMMIT(MB_EMPTYA + 8 * sahi);
            TCGEN05_COMMIT(MB_EMPTYB + 8 * sblo);

            MBARRIER_WAIT_PARITY(MB_FULLA + 8 * salo, (jalo / NSA) & 1);
            // P2 = Alo * Bhi   (last use of Alo, Bhi)
#pragma unroll
            for (int k = 0; k < 4; ++k) {
                mma_f16_ss(tmem,       al0 + k * 2, bh + k * 2, GEMM_IDESC, 1u);
                mma_f16_ss(tmem + 256, al1 + k * 2, bh + k * 2, GEMM_IDESC, 1u);
            }
            TCGEN05_COMMIT(MB_EMPTYA + 8 * salo);
            TCGEN05_COMMIT(MB_EMPTYB + 8 * sbhi);
        }
        TCGEN05_COMMIT(MB_DONE);   // fires when all MMAs retire
    }

    // ---------------- epilogue: all warps ------------------------------------
    MBARRIER_WAIT_PARITY(MB_DONE, 0);
    TCGEN05_FENCE_AFTER();
    {
        const int half = wid >> 2;
        const int sub  = wid & 3;
        const uint32_t lane_off = ((uint32_t)sub) << 21;
        const int m = m0 + half * 128 + sub * 32 + lid;
        float* orow = out + (size_t)m * OUT_DIM + n0;
#pragma unroll
        for (int cc = 0; cc < 8; ++cc) {
            uint32_t r[32];
            TCGEN05_LD_32X32B_X32(
                r, tmem + lane_off + (uint32_t)(half * 256 + cc * 32));
            TCGEN05_WAIT_LD();
            float* dst = orow + cc * 32;
#pragma unroll
            for (int q = 0; q < 8; ++q) {
                float4 v;
                v.x = __uint_as_float(r[4 * q + 0]);
                v.y = __uint_as_float(r[4 * q + 1]);
                v.z = __uint_as_float(r[4 * q + 2]);
                v.w = __uint_as_float(r[4 * q + 3]);
                ((float4*)dst)[q] = v;
            }
        }
        TCGEN05_FENCE_BEFORE();
    }

    __syncthreads();
    if (wid == 0) TCGEN05_DEALLOC(tmem, 512);
#else
    (void)out; (void)mxhi; (void)mxlo; (void)mwhi; (void)mwlo;
#endif
}

// ============================================================================
// GEMM (mma.sync fallback) — unchanged; runs only if g_has_tc == 0
// ============================================================================
__global__ __launch_bounds__(512, 1)
void gemm_fb_kernel(float* __restrict__ out) {
    if (g_has_tc) return;

    extern __shared__ char smem[];
    const uint32_t smem_base = smem_to_u32(smem);
    const int tid = threadIdx.x;
    const int wid = tid >> 5;
    const int lid = tid & 31;
    const int wm = wid & 3;
    const int wn = wid >> 2;
    const int m0 = blockIdx.y * FB_TM;
    const int n0 = blockIdx.x * FB_TN;

    float acc[2][8][4];
#pragma unroll
    for (int i = 0; i < 2; ++i)
#pragma unroll
        for (int j = 0; j < 8; ++j)
#pragma unroll
            for (int k = 0; k < 4; ++k) acc[i][j][k] = 0.f;

    const int ar  = wm * 32 + (lid & 15);
    const int ca  = lid >> 4;
    const int axr = ar & 7;
    const int bn  = wn * 64 + (lid & 7) + ((lid >> 4) << 3);
    const int kb  = (lid >> 3) & 1;
    const int bxr = bn & 7;

    auto load_chunk = [&](int c) {
        const int st = c & 3;
        const int s  = c >> 6;
        const int k0 = (c & 63) << 6;
        const __nv_bfloat16* Ab = ((s == 1) ? g_xlo : g_xhi) + (size_t)m0 * IN_DIM + k0;
        const __nv_bfloat16* Bb = ((s == 2) ? g_wlo : g_whi) + (size_t)n0 * IN_DIM + k0;
        const uint32_t sa = smem_base + st * FB_STAGE;
        const uint32_t sb = sa + FB_A_BYTES;
#pragma unroll
        for (int it = 0; it < 2; ++it) {
            int i = tid + it * 512;
            int row = i >> 3, j = i & 7;
            uint32_t dst = sa + row * 128 + ((uint32_t)(j ^ (row & 7)) << 4);
            cp_async16(dst, Ab + (size_t)row * IN_DIM + j * 8);
        }
#pragma unroll
        for (int it = 0; it < 4; ++it) {
            int i = tid + it * 512;
            int row = i >> 3, j = i & 7;
            uint32_t dst = sb + row * 128 + ((uint32_t)(j ^ (row & 7)) << 4);
            cp_async16(dst, Bb + (size_t)row * IN_DIM + j * 8);
        }
        CP_COMMIT();
    };

    load_chunk(0);
    load_chunk(1);
    load_chunk(2);

    for (int c = 0; c < FB_NCH; ++c) {
        const int rem = FB_NCH - 1 - c;
        if (rem >= 2)      CP_WAIT(2);
        else if (rem == 1) CP_WAIT(1);
        else               CP_WAIT(0);
        __syncthreads();
        if (c + 3 < FB_NCH) load_chunk(c + 3);

        const uint32_t sa = smem_base + (c & 3) * FB_STAGE;
        const uint32_t sb = sa + FB_A_BYTES;

#pragma unroll
        for (int s = 0; s < 4; ++s) {
            uint32_t a[2][4];
#pragma unroll
            for (int mb = 0; mb < 2; ++mb) {
                uint32_t addr = sa + (ar + mb * 16) * 128
                              + ((uint32_t)(((s << 1) + ca) ^ axr) << 4);
                ldsm_x4(a[mb], addr);
            }
#pragma unroll
            for (int nb = 0; nb < 4; ++nb) {
                uint32_t b[4];
                uint32_t addr = sb + (bn + nb * 16) * 128
                              + ((uint32_t)(((s << 1) + kb) ^ bxr) << 4);
                ldsm_x4(b, addr);
#pragma unroll
                for (int mb = 0; mb < 2; ++mb) {
                    mma16816(acc[mb][nb * 2 + 0], a[mb], b + 0);
                    mma16816(acc[mb][nb * 2 + 1], a[mb], b + 2);
                }
            }
        }
    }

#pragma unroll
    for (int mb = 0; mb < 2; ++mb) {
        const int r0 = m0 + wm * 32 + mb * 16 + (lid >> 2);
#pragma unroll
        for (int nb8 = 0; nb8 < 8; ++nb8) {
            const int col = n0 + wn * 64 + nb8 * 8 + (lid & 3) * 2;
            float2 v0; v0.x = acc[mb][nb8][0]; v0.y = acc[mb][nb8][1];
            float2 v1; v1.x = acc[mb][nb8][2]; v1.y = acc[mb][nb8][3];
            *(float2*)(out + (size_t)r0 * OUT_DIM + col)       = v0;
            *(float2*)(out + (size_t)(r0 + 8) * OUT_DIM + col) = v1;
        }
    }
}

// ============================================================================
// Host: tensor-map construction via driver entry point (no -lcuda link)
// ============================================================================
typedef CUresult (*PFN_tmeTiled)(
    CUtensorMap*, CUtensorMapDataType, unsigned int, void*,
    const unsigned long long*, const unsigned long long*,
    const unsigned int*, const unsigned int*,
    CUtensorMapInterleave, CUtensorMapSwizzle,
    CUtensorMapL2promotion, CUtensorMapFloatOOBfill);

static void make_map(PFN_tmeTiled enc, CUtensorMap* m, void* base,
                     unsigned long long rows) {
    unsigned long long dims[2]    = {IN_DIM, rows};
    unsigned long long strides[1] = {IN_DIM * sizeof(__nv_bfloat16)};
    unsigned int box[2]  = {64, 256};
    unsigned int es[2]   = {1, 1};
    enc(m, CU_TENSOR_MAP_DATA_TYPE_BFLOAT16, 2, base, dims, strides, box, es,
        CU_TENSOR_MAP_INTERLEAVE_NONE, CU_TENSOR_MAP_SWIZZLE_128B,
        CU_TENSOR_MAP_L2_PROMOTION_L2_128B, CU_TENSOR_MAP_FLOAT_OOB_FILL_NONE);
}

extern "C" void kernel_launch(void* const* d_in, const int* in_sizes, int n_in,
                              void* d_out, int out_size) {
    (void)in_sizes; (void)n_in; (void)out_size;
    const float* x      = (const float*)d_in[0];
    const float* W_org  = (const float*)d_in[1];
    const float* q_w    = (const float*)d_in[2];
    const float* p_w    = (const float*)d_in[3];
    const float* lam    = (const float*)d_in[4];
    const float* bq_w   = (const float*)d_in[5];
    const float* bp_w   = (const float*)d_in[6];
    const float* blam   = (const float*)d_in[7];
    float* out = (float*)d_out;

    cudaFuncSetAttribute(gemm_tc_kernel,
                         cudaFuncAttributeMaxDynamicSharedMemorySize, SMEM_TC);
    cudaFuncSetAttribute(gemm_fb_kernel,
                         cudaFuncAttributeMaxDynamicSharedMemorySize, SMEM_FB);

    // tensor maps (host-side, pure function calls — graph-capture safe)
    void* fn = nullptr;
    cudaDriverEntryPointQueryResult qst;
    cudaGetDriverEntryPoint("cuTensorMapEncodeTiled", &fn,
                            cudaEnableDefault, &qst);
    PFN_tmeTiled enc = (PFN_tmeTiled)fn;

    void *p_xhi, *p_xlo, *p_whi, *p_wlo;
    cudaGetSymbolAddress(&p_xhi, g_xhi);
    cudaGetSymbolAddress(&p_xlo, g_xlo);
    cudaGetSymbolAddress(&p_whi, g_whi);
    cudaGetSymbolAddress(&p_wlo, g_wlo);

    CUtensorMap mxhi{}, mxlo{}, mwhi{}, mwlo{};
    make_map(enc, &mxhi, p_xhi, M_TOTAL);
    make_map(enc, &mxlo, p_xlo, M_TOTAL);
    make_map(enc, &mwhi, p_whi, OUT_DIM);
    make_map(enc, &mwlo, p_wlo, OUT_DIM);

    probe_kernel<<<1, 1>>>();
    build_aprime_kernel<<<(OUT_DIM * 2 * RANK) / 256, 256>>>(p_w, lam, bp_w, blam);
    fold_w_kernel<<<dim3(IN_DIM / 1024, OUT_DIM / 16), 256>>>(W_org, q_w, bq_w);
    split_x_kernel<<<(int)(((size_t)M_TOTAL * IN_DIM / 4) / 256), 256>>>(
        (const float4*)x);

    gemm_tc_kernel<<<dim3(OUT_DIM / TILE_N, M_TOTAL / TILE_M), 256, SMEM_TC>>>(
        out, mxhi, mxlo, mwhi, mwlo);
    gemm_fb_kernel<<<dim3(OUT_DIM / FB_TN, M_TOTAL / FB_TM), 512, SMEM_FB>>>(out);
}